// round 2
// baseline (speedup 1.0000x reference)
#include <cuda_runtime.h>
#include <cuda_fp8.h>

// COAT Coat_quantize_bgn forward, group_size = 16.
// x: [4, 4096, 4096] f32 (67108864 elems)
// out layout (concat, f32): [x passthrough (n)] [Q (n)] [Oscale (n/16)]
//
// 4 threads per group-of-16: each thread owns one float4.
// Warp = 8 groups, fully coalesced 512B loads/stores.

#define COAT_E4M3_MAX 448.0f

__global__ void __launch_bounds__(256)
coat_quantize_kernel(const float4* __restrict__ x4,
                     float4* __restrict__ out_x4,
                     float4* __restrict__ out_q4,
                     float* __restrict__ out_s,
                     int n4)
{
    int i = blockIdx.x * blockDim.x + threadIdx.x;
    if (i >= n4) return;

    float4 v = x4[i];

    // per-thread amax over 4 elems
    float a = fmaxf(fmaxf(fabsf(v.x), fabsf(v.y)),
                    fmaxf(fabsf(v.z), fabsf(v.w)));
    // reduce across the 4 lanes of this group (lanes i, i^1, i^2, i^3)
    a = fmaxf(a, __shfl_xor_sync(0xffffffffu, a, 1));
    a = fmaxf(a, __shfl_xor_sync(0xffffffffu, a, 2));

    // scale = amax / 448, with all-zero-group -> 1.0  (IEEE div to match ref)
    float scale = (a == 0.0f) ? 1.0f : __fdiv_rn(a, COAT_E4M3_MAX);

    // quantize: q = fp8_e4m3(v / scale) re-expressed as f32.
    // __nv_fp8_e4m3 ctor = cvt.rn.satfinite.e4m3 (matches XLA f8e4m3fn cast).
    float4 q;
    q.x = float(__nv_fp8_e4m3(__fdiv_rn(v.x, scale)));
    q.y = float(__nv_fp8_e4m3(__fdiv_rn(v.y, scale)));
    q.z = float(__nv_fp8_e4m3(__fdiv_rn(v.z, scale)));
    q.w = float(__nv_fp8_e4m3(__fdiv_rn(v.w, scale)));

    out_x4[i] = v;      // passthrough
    out_q4[i] = q;      // quantized values on fp8 grid, f32 view

    // one scale per group (4 threads) — lane (i&3)==0 writes
    if ((i & 3) == 0)
        out_s[i >> 2] = scale;
}

extern "C" void kernel_launch(void* const* d_in, const int* in_sizes, int n_in,
                              void* d_out, int out_size)
{
    const float* x = (const float*)d_in[0];
    int n = in_sizes[0];              // 67108864
    int n4 = n >> 2;                  // float4 count = 16777216

    float* out = (float*)d_out;
    float4* out_x4 = (float4*)out;              // [n] passthrough
    float4* out_q4 = (float4*)(out + (size_t)n);// [n] Q
    float*  out_s  = out + 2 * (size_t)n;       // [n/16] Oscale

    int threads = 256;
    int blocks = (n4 + threads - 1) / threads;  // 65536
    coat_quantize_kernel<<<blocks, threads>>>(
        (const float4*)x, out_x4, out_q4, out_s, n4);
}